// round 6
// baseline (speedup 1.0000x reference)
#include <cuda_runtime.h>

#define B_N   4096
#define S_N   5
#define D_N   64
#define HS_N  961
#define VSA_N 1024
#define HP_N  1088   // padded reversed-kernel row length (needs 1087)
#define LN_EPS_F 0.001f

// Scratch (device globals; no allocation allowed)
__device__ float g_hrp[S_N * HP_N];   // reversed + zero-padded h, per s
__device__ float g_sp[S_N * VSA_N];   // batch-invariant symbols path output

__device__ __forceinline__ float wredf(float v) {
    v += __shfl_xor_sync(0xffffffffu, v, 16);
    v += __shfl_xor_sync(0xffffffffu, v, 8);
    v += __shfl_xor_sync(0xffffffffu, v, 4);
    v += __shfl_xor_sync(0xffffffffu, v, 2);
    v += __shfl_xor_sync(0xffffffffu, v, 1);
    return v;
}

__device__ __forceinline__ float siluf(float z) {
    // z * sigmoid(z); __expf overflow for very negative z gives denom=inf -> 0, correct limit
    return __fdividef(z, 1.f + __expf(-z));
}

__device__ __forceinline__ float sgnf(float x) {
    return (x > 0.f) ? 1.f : ((x < 0.f) ? -1.f : 0.f);
}

// ---- packed fp32x2 helpers (sm_103a FFMA2 path) ---------------------------
__device__ __forceinline__ unsigned long long pk2(float lo, float hi) {
    unsigned long long r;
    asm("mov.b64 %0, {%1, %2};" : "=l"(r) : "f"(lo), "f"(hi));
    return r;
}
__device__ __forceinline__ void fma2(unsigned long long& acc,
                                     unsigned long long a,
                                     unsigned long long b) {
    asm("fma.rn.f32x2 %0, %1, %2, %0;" : "+l"(acc) : "l"(a), "l"(b));
}
__device__ __forceinline__ float hsum2(unsigned long long acc) {
    float lo, hi;
    asm("mov.b64 {%0, %1}, %2;" : "=f"(lo), "=f"(hi) : "l"(acc));
    return lo + hi;
}

// ---------------------------------------------------------------------------
// Kernel 0: build g_hrp (reversed, padded h) and g_sp (symbols conv+silu+LN).
// grid = S_N blocks, 256 threads. Tiny; stays scalar.
// ---------------------------------------------------------------------------
__global__ void prep_kernel(const float* __restrict__ h,
                            const float* __restrict__ sym,
                            const float* __restrict__ gamma,
                            const float* __restrict__ beta) {
    const int s   = blockIdx.x;
    const int tid = threadIdx.x;
    const int wid = tid >> 5, lane = tid & 31;

    __shared__ float sx[D_N];
    __shared__ float sh[HP_N];
    __shared__ float sy[VSA_N];
    __shared__ float sred[16];
    __shared__ float sstat[2];

    if (tid < D_N) sx[tid] = sym[s * D_N + tid];
    for (int j = tid; j < HP_N; j += 256) {
        float v = 0.f;
        if (j >= 63 && j <= 1023) v = h[s * HS_N + (1023 - j)];
        sh[j] = v;
        g_hrp[s * HP_N + j] = v;
    }
    __syncthreads();

    float ls = 0.f, lq = 0.f;
    #pragma unroll
    for (int c = 0; c < 4; c++) {
        const int o = tid + c * 256;
        float a = 0.f;
        #pragma unroll
        for (int i = 0; i < D_N; i++) a = fmaf(sx[i], sh[o + 63 - i], a);
        const float v = siluf(a);
        sy[o] = v;
        ls += v; lq += v * v;
    }
    ls = wredf(ls); lq = wredf(lq);
    if (lane == 0) { sred[wid] = ls; sred[wid + 8] = lq; }
    __syncthreads();
    if (tid == 0) {
        float S1 = 0.f, S2 = 0.f;
        for (int w = 0; w < 8; w++) { S1 += sred[w]; S2 += sred[w + 8]; }
        const float mu  = S1 * (1.f / 1024.f);
        const float var = S2 * (1.f / 1024.f) - mu * mu;
        sstat[0] = mu;
        sstat[1] = rsqrtf(var + LN_EPS_F);
    }
    __syncthreads();
    const float mu = sstat[0], rs = sstat[1];
    #pragma unroll
    for (int c = 0; c < 4; c++) {
        const int o = tid + c * 256;
        g_sp[s * VSA_N + o] = (sy[o] - mu) * rs * gamma[o] + beta[o];
    }
}

// ---------------------------------------------------------------------------
// Kernel 1: fully fused per-batch pipeline.
// grid = B_N blocks, 256 threads. One CTA = one batch element.
// ---------------------------------------------------------------------------
__global__ __launch_bounds__(256) void main_kernel(
    const float* __restrict__ values,
    const float* __restrict__ gamma,
    const float* __restrict__ beta,
    float* __restrict__ out) {
    const int b   = blockIdx.x;
    const int tid = threadIdx.x;
    const int wid = tid >> 5, lane = tid & 31;

    __shared__ __align__(16) float s_h[S_N * HP_N];      // 21760 B
    __shared__ __align__(16) float s_x[S_N * D_N];       //  1280 B
    __shared__ __align__(16) float s_vp[S_N * VSA_N];    // 20480 B
    __shared__ float s_red[8 * 25];        //   800 B (reused: LN partials, score partials)
    __shared__ float s_sc[25];
    __shared__ float s_w[25];
    __shared__ float s_stats[2 * S_N];

    for (int j = tid; j < S_N * HP_N; j += 256) s_h[j] = g_hrp[j];
    for (int j = tid; j < S_N * D_N;  j += 256) s_x[j] = values[b * (S_N * D_N) + j];
    __syncthreads();

    // ---- Phase 1: conv + silu, per-s LN partial sums -----------------------
    // y[o+k] = sum_i x[i]*hw[o+k+63-i], hw = reversed padded h.
    // Packed FFMA2 over the reduction dim: even-i and odd-i partial sums live
    // in the lo/hi lanes of a 64-bit accumulator; x pairs (x[i],x[i+1]) come
    // pre-packed from a 16B shared load; h pairs are packed from the sliding
    // float4 register window (6 distinct packs per 4-tap block, 2 reused).
    #pragma unroll
    for (int s = 0; s < S_N; s++) {
        const int o = tid * 4;
        const float* xs = s_x + s * D_N;
        const float* hp = s_h + s * HP_N;
        float4 p = *(const float4*)(hp + o + 64);   // hw[o+64 .. o+67]
        unsigned long long a0 = 0ull, a1 = 0ull, a2 = 0ull, a3 = 0ull;
        #pragma unroll
        for (int i = 0; i < 64; i += 4) {
            const float4 hv = *(const float4*)(hp + o + 60 - i); // hw[o+60-i .. o+63-i]
            const ulonglong2 xd = *(const ulonglong2*)(xs + i);  // (x[i],x[i+1]),(x[i+2],x[i+3])
            // distinct h pairs for this block (lo multiplies the even-i lane)
            const unsigned long long h_wz = pk2(hv.w, hv.z);   // (hw[o+63-i], hw[o+62-i])
            const unsigned long long h_pxw = pk2(p.x, hv.w);   // (hw[o+64-i], hw[o+63-i])
            const unsigned long long h_pyx = pk2(p.y, p.x);    // (hw[o+65-i], hw[o+64-i])
            const unsigned long long h_pzy = pk2(p.z, p.y);    // (hw[o+66-i], hw[o+65-i])
            const unsigned long long h_yx = pk2(hv.y, hv.x);   // (hw[o+61-i], hw[o+60-i])
            const unsigned long long h_zy = pk2(hv.z, hv.y);   // (hw[o+62-i], hw[o+61-i])
            // i-pair A: taps i, i+1
            fma2(a0, xd.x, h_wz);
            fma2(a1, xd.x, h_pxw);
            fma2(a2, xd.x, h_pyx);
            fma2(a3, xd.x, h_pzy);
            // i-pair B: taps i+2, i+3
            fma2(a0, xd.y, h_yx);
            fma2(a1, xd.y, h_zy);
            fma2(a2, xd.y, h_wz);   // reuse
            fma2(a3, xd.y, h_pxw);  // reuse
            p = hv;
        }
        const float v0 = siluf(hsum2(a0));
        const float v1 = siluf(hsum2(a1));
        const float v2 = siluf(hsum2(a2));
        const float v3 = siluf(hsum2(a3));
        float4 vo; vo.x = v0; vo.y = v1; vo.z = v2; vo.w = v3;
        *(float4*)(s_vp + s * VSA_N + o) = vo;

        float ls = v0 + v1 + v2 + v3;
        float lq = v0 * v0 + v1 * v1 + v2 * v2 + v3 * v3;
        ls = wredf(ls); lq = wredf(lq);
        if (lane == 0) { s_red[s * 16 + wid] = ls; s_red[s * 16 + 8 + wid] = lq; }
    }
    __syncthreads();
    if (tid < S_N) {
        float S1 = 0.f, S2 = 0.f;
        for (int w = 0; w < 8; w++) { S1 += s_red[tid * 16 + w]; S2 += s_red[tid * 16 + 8 + w]; }
        const float mu  = S1 * (1.f / 1024.f);
        const float var = S2 * (1.f / 1024.f) - mu * mu;
        s_stats[tid * 2]     = mu;
        s_stats[tid * 2 + 1] = rsqrtf(var + LN_EPS_F);
    }
    __syncthreads();

    // ---- Phase 2: apply LayerNorm in place (float4, s == c) ---------------
    {
        const float4 g4 = *(const float4*)(gamma + 4 * tid);
        const float4 b4 = *(const float4*)(beta  + 4 * tid);
        #pragma unroll
        for (int c = 0; c < S_N; c++) {
            const int idx = c * VSA_N + 4 * tid;
            const float mu = s_stats[c * 2], rs = s_stats[c * 2 + 1];
            float4 v = *(float4*)(s_vp + idx);
            v.x = (v.x - mu) * rs * g4.x + b4.x;
            v.y = (v.y - mu) * rs * g4.y + b4.y;
            v.z = (v.z - mu) * rs * g4.z + b4.z;
            v.w = (v.w - mu) * rs * g4.w + b4.w;
            *(float4*)(s_vp + idx) = v;
        }
    }
    __syncthreads();

    // ---- Phase 3: scores[j][i] = mean_v sign(vp[i])*sign(vp[i]+sp[j]) -----
    float sc[25];
    #pragma unroll
    for (int q = 0; q < 25; q++) sc[q] = 0.f;
    #pragma unroll
    for (int c = 0; c < 4; c++) {
        const int v = c * 256 + tid;
        float vv[5], si[5], sv[5];
        #pragma unroll
        for (int i = 0; i < 5; i++) { vv[i] = s_vp[i * 1024 + v]; si[i] = sgnf(vv[i]); }
        #pragma unroll
        for (int j = 0; j < 5; j++) sv[j] = g_sp[j * 1024 + v];
        #pragma unroll
        for (int j = 0; j < 5; j++)
            #pragma unroll
            for (int i = 0; i < 5; i++)
                sc[j * 5 + i] += si[i] * sgnf(vv[i] + sv[j]);
    }
    #pragma unroll
    for (int q = 0; q < 25; q++) {
        const float r = wredf(sc[q]);
        if (lane == 0) s_red[wid * 25 + q] = r;
    }
    __syncthreads();
    if (tid < 25) {
        float t = 0.f;
        for (int w = 0; w < 8; w++) t += s_red[w * 25 + tid];
        s_sc[tid] = t * (1.f / 1024.f);
    }
    __syncthreads();

    // ---- Phase 4: softmax over i (5-wide), per j --------------------------
    if (tid < 5) {
        const int j = tid;
        float m = -1e30f;
        #pragma unroll
        for (int i = 0; i < 5; i++) m = fmaxf(m, s_sc[j * 5 + i]);
        float e[5], sum = 0.f;
        #pragma unroll
        for (int i = 0; i < 5; i++) { e[i] = __expf(s_sc[j * 5 + i] - m); sum += e[i]; }
        const float inv = __frcp_rn(sum);
        #pragma unroll
        for (int i = 0; i < 5; i++) s_w[j * 5 + i] = e[i] * inv;
    }
    __syncthreads();

    // ---- Phase 5: att = scores @ vp ; out = silu(att * sp) (float4, j==c) --
    #pragma unroll
    for (int c = 0; c < S_N; c++) {
        const int idx = c * VSA_N + 4 * tid;
        float4 att = make_float4(0.f, 0.f, 0.f, 0.f);
        #pragma unroll
        for (int i = 0; i < 5; i++) {
            const float w = s_w[c * 5 + i];
            const float4 v = *(const float4*)(s_vp + i * VSA_N + 4 * tid);
            att.x = fmaf(w, v.x, att.x);
            att.y = fmaf(w, v.y, att.y);
            att.z = fmaf(w, v.z, att.z);
            att.w = fmaf(w, v.w, att.w);
        }
        const float4 sp4 = *(const float4*)(g_sp + idx);
        float4 o4;
        o4.x = siluf(att.x * sp4.x);
        o4.y = siluf(att.y * sp4.y);
        o4.z = siluf(att.z * sp4.z);
        o4.w = siluf(att.w * sp4.w);
        *(float4*)(out + b * (S_N * VSA_N) + idx) = o4;
    }
}

extern "C" void kernel_launch(void* const* d_in, const int* in_sizes, int n_in,
                              void* d_out, int out_size) {
    const float* values = (const float*)d_in[0];
    const float* h      = (const float*)d_in[1];
    const float* sym    = (const float*)d_in[2];
    const float* gamma  = (const float*)d_in[3];
    const float* beta   = (const float*)d_in[4];
    float* out = (float*)d_out;

    prep_kernel<<<S_N, 256>>>(h, sym, gamma, beta);
    main_kernel<<<B_N, 256>>>(values, gamma, beta, out);
}

// round 9
// speedup vs baseline: 1.1100x; 1.1100x over previous
#include <cuda_runtime.h>

#define B_N   4096
#define S_N   5
#define D_N   64
#define HS_N  961
#define VSA_N 1024
#define HP_N  1088   // padded reversed-kernel row length (needs 1087)
#define LN_EPS_F 0.001f

// Scratch (device globals; no allocation allowed)
__device__ float g_hrp[S_N * HP_N];   // reversed + zero-padded h, per s
__device__ float g_sp[S_N * VSA_N];   // batch-invariant symbols path output

__device__ __forceinline__ float wredf(float v) {
    v += __shfl_xor_sync(0xffffffffu, v, 16);
    v += __shfl_xor_sync(0xffffffffu, v, 8);
    v += __shfl_xor_sync(0xffffffffu, v, 4);
    v += __shfl_xor_sync(0xffffffffu, v, 2);
    v += __shfl_xor_sync(0xffffffffu, v, 1);
    return v;
}

__device__ __forceinline__ float siluf(float z) {
    return __fdividef(z, 1.f + __expf(-z));
}

// ---- packed fp32x2 helpers (sm_103a FFMA2 path) ---------------------------
__device__ __forceinline__ unsigned long long pk2(float lo, float hi) {
    unsigned long long r;
    asm("mov.b64 %0, {%1, %2};" : "=l"(r) : "f"(lo), "f"(hi));
    return r;
}
__device__ __forceinline__ void fma2(unsigned long long& acc,
                                     unsigned long long a,
                                     unsigned long long b) {
    asm("fma.rn.f32x2 %0, %1, %2, %0;" : "+l"(acc) : "l"(a), "l"(b));
}
__device__ __forceinline__ float hsum2(unsigned long long acc) {
    float lo, hi;
    asm("mov.b64 {%0, %1}, %2;" : "=f"(lo), "=f"(hi) : "l"(acc));
    return lo + hi;
}

// ---------------------------------------------------------------------------
// Kernel 0: build g_hrp (reversed, padded h) and g_sp (symbols conv+silu+LN).
// ---------------------------------------------------------------------------
__global__ void prep_kernel(const float* __restrict__ h,
                            const float* __restrict__ sym,
                            const float* __restrict__ gamma,
                            const float* __restrict__ beta) {
    const int s   = blockIdx.x;
    const int tid = threadIdx.x;
    const int wid = tid >> 5, lane = tid & 31;

    __shared__ float sx[D_N];
    __shared__ float sh[HP_N];
    __shared__ float sy[VSA_N];
    __shared__ float sred[16];
    __shared__ float sstat[2];

    if (tid < D_N) sx[tid] = sym[s * D_N + tid];
    for (int j = tid; j < HP_N; j += 256) {
        float v = 0.f;
        if (j >= 63 && j <= 1023) v = h[s * HS_N + (1023 - j)];
        sh[j] = v;
        g_hrp[s * HP_N + j] = v;
    }
    __syncthreads();

    float ls = 0.f, lq = 0.f;
    #pragma unroll
    for (int c = 0; c < 4; c++) {
        const int o = tid + c * 256;
        float a = 0.f;
        #pragma unroll
        for (int i = 0; i < D_N; i++) a = fmaf(sx[i], sh[o + 63 - i], a);
        const float v = siluf(a);
        sy[o] = v;
        ls += v; lq += v * v;
    }
    ls = wredf(ls); lq = wredf(lq);
    if (lane == 0) { sred[wid] = ls; sred[wid + 8] = lq; }
    __syncthreads();
    if (tid == 0) {
        float S1 = 0.f, S2 = 0.f;
        for (int w = 0; w < 8; w++) { S1 += sred[w]; S2 += sred[w + 8]; }
        const float mu  = S1 * (1.f / 1024.f);
        const float var = S2 * (1.f / 1024.f) - mu * mu;
        sstat[0] = mu;
        sstat[1] = rsqrtf(var + LN_EPS_F);
    }
    __syncthreads();
    const float mu = sstat[0], rs = sstat[1];
    #pragma unroll
    for (int c = 0; c < 4; c++) {
        const int o = tid + c * 256;
        g_sp[s * VSA_N + o] = (sy[o] - mu) * rs * gamma[o] + beta[o];
    }
}

// ---------------------------------------------------------------------------
// Kernel 1: fused pipeline, TWO batch elements per CTA.
// grid = B_N/2 blocks, 256 threads.
// ---------------------------------------------------------------------------
__global__ __launch_bounds__(256) void main_kernel(
    const float* __restrict__ values,
    const float* __restrict__ gamma,
    const float* __restrict__ beta,
    float* __restrict__ out) {
    const int b0  = blockIdx.x * 2;
    const int tid = threadIdx.x;
    const int wid = tid >> 5, lane = tid & 31;

    __shared__ __align__(16) float s_vp[2][S_N * VSA_N]; // 40960 B
    __shared__ __align__(16) float s_x[2][S_N * D_N];    //  2560 B
    __shared__ float s_red[S_N][8][4];                   //   640 B
    __shared__ int   s_ired[8][25];                      //   800 B
    __shared__ float s_sc[2][25];                        //   200 B
    __shared__ float s_w[2][25];                         //   200 B
    __shared__ float s_stats[2][S_N][2];                 //    80 B

    for (int j = tid; j < 2 * S_N * D_N; j += 256) {
        const int bb = j / (S_N * D_N), r = j % (S_N * D_N);
        s_x[bb][r] = values[(b0 + bb) * (S_N * D_N) + r];
    }
    __syncthreads();

    // ---- Phase 1: conv + silu for both batches; one h window feeds both ---
    // y[o+k] = sum_i x[i]*hw[o+k+63-i]. FFMA2 packs the reduction dim
    // (even/odd taps in lo/hi lanes); the 6 h-pair packs per iteration are
    // shared across both batches (16 FFMA2 per 6 packs + 1 h load).
    #pragma unroll
    for (int s = 0; s < S_N; s++) {
        const int o = tid * 4;
        const float* hp = g_hrp + s * HP_N + o;   // L1-cached global reads
        const float* x0 = s_x[0] + s * D_N;
        const float* x1 = s_x[1] + s * D_N;
        float4 p = __ldg((const float4*)(hp + 64));   // hw[o+64 .. o+67]
        unsigned long long a0 = 0ull, a1 = 0ull, a2 = 0ull, a3 = 0ull;
        unsigned long long c0 = 0ull, c1 = 0ull, c2 = 0ull, c3 = 0ull;
        #pragma unroll
        for (int i = 0; i < 64; i += 4) {
            const float4 hv = __ldg((const float4*)(hp + 60 - i)); // hw[o+60-i..o+63-i]
            const ulonglong2 xd0 = *(const ulonglong2*)(x0 + i);
            const ulonglong2 xd1 = *(const ulonglong2*)(x1 + i);
            const unsigned long long h_wz  = pk2(hv.w, hv.z);
            const unsigned long long h_pxw = pk2(p.x, hv.w);
            const unsigned long long h_pyx = pk2(p.y, p.x);
            const unsigned long long h_pzy = pk2(p.z, p.y);
            const unsigned long long h_yx  = pk2(hv.y, hv.x);
            const unsigned long long h_zy  = pk2(hv.z, hv.y);
            // batch 0: taps (i,i+1) then (i+2,i+3)
            fma2(a0, xd0.x, h_wz);  fma2(a1, xd0.x, h_pxw);
            fma2(a2, xd0.x, h_pyx); fma2(a3, xd0.x, h_pzy);
            fma2(a0, xd0.y, h_yx);  fma2(a1, xd0.y, h_zy);
            fma2(a2, xd0.y, h_wz);  fma2(a3, xd0.y, h_pxw);
            // batch 1
            fma2(c0, xd1.x, h_wz);  fma2(c1, xd1.x, h_pxw);
            fma2(c2, xd1.x, h_pyx); fma2(c3, xd1.x, h_pzy);
            fma2(c0, xd1.y, h_yx);  fma2(c1, xd1.y, h_zy);
            fma2(c2, xd1.y, h_wz);  fma2(c3, xd1.y, h_pxw);
            p = hv;
        }
        float4 v0, v1;
        v0.x = siluf(hsum2(a0)); v0.y = siluf(hsum2(a1));
        v0.z = siluf(hsum2(a2)); v0.w = siluf(hsum2(a3));
        v1.x = siluf(hsum2(c0)); v1.y = siluf(hsum2(c1));
        v1.z = siluf(hsum2(c2)); v1.w = siluf(hsum2(c3));
        *(float4*)(s_vp[0] + s * VSA_N + o) = v0;
        *(float4*)(s_vp[1] + s * VSA_N + o) = v1;

        float ls0 = wredf(v0.x + v0.y + v0.z + v0.w);
        float lq0 = wredf(v0.x*v0.x + v0.y*v0.y + v0.z*v0.z + v0.w*v0.w);
        float ls1 = wredf(v1.x + v1.y + v1.z + v1.w);
        float lq1 = wredf(v1.x*v1.x + v1.y*v1.y + v1.z*v1.z + v1.w*v1.w);
        if (lane == 0) {
            s_red[s][wid][0] = ls0; s_red[s][wid][1] = lq0;
            s_red[s][wid][2] = ls1; s_red[s][wid][3] = lq1;
        }
    }
    __syncthreads();
    if (tid < 10) {
        const int bb = tid & 1, s = tid >> 1;
        float S1 = 0.f, S2 = 0.f;
        for (int w = 0; w < 8; w++) {
            S1 += s_red[s][w][bb * 2];
            S2 += s_red[s][w][bb * 2 + 1];
        }
        const float mu  = S1 * (1.f / 1024.f);
        const float var = S2 * (1.f / 1024.f) - mu * mu;
        s_stats[bb][s][0] = mu;
        s_stats[bb][s][1] = rsqrtf(var + LN_EPS_F);
    }
    __syncthreads();

    // ---- Phase 2: apply LayerNorm in place (float4) -----------------------
    {
        const float4 g4 = *(const float4*)(gamma + 4 * tid);
        const float4 bt4 = *(const float4*)(beta + 4 * tid);
        #pragma unroll
        for (int bb = 0; bb < 2; bb++) {
            #pragma unroll
            for (int c = 0; c < S_N; c++) {
                const int idx = c * VSA_N + 4 * tid;
                const float mu = s_stats[bb][c][0], rs = s_stats[bb][c][1];
                float4 v = *(float4*)(s_vp[bb] + idx);
                v.x = (v.x - mu) * rs * g4.x + bt4.x;
                v.y = (v.y - mu) * rs * g4.y + bt4.y;
                v.z = (v.z - mu) * rs * g4.z + bt4.z;
                v.w = (v.w - mu) * rs * g4.w + bt4.w;
                *(float4*)(s_vp[bb] + idx) = v;
            }
        }
    }
    __syncthreads();

    // ---- Phase 3: scores via ballot+popc ----------------------------------
    // sign(vp)*sign(vp+sp) = +1 iff (vp>0)==(vp+sp>0) (zeros: measure-zero).
    // Counts for both batches packed 16/16 into one int accumulator.
    {
        int acc[25];
        #pragma unroll
        for (int q = 0; q < 25; q++) acc[q] = 0;
        #pragma unroll
        for (int c = 0; c < 4; c++) {
            const int v = c * 256 + tid;
            float sv[5], v0[5], v1[5];
            bool q0[5], q1[5];
            #pragma unroll
            for (int i = 0; i < 5; i++) {
                v0[i] = s_vp[0][i * VSA_N + v]; q0[i] = v0[i] > 0.f;
                v1[i] = s_vp[1][i * VSA_N + v]; q1[i] = v1[i] > 0.f;
            }
            #pragma unroll
            for (int j = 0; j < 5; j++) sv[j] = __ldg(g_sp + j * VSA_N + v);
            #pragma unroll
            for (int j = 0; j < 5; j++) {
                #pragma unroll
                for (int i = 0; i < 5; i++) {
                    const bool m0 = ((v0[i] + sv[j]) > 0.f) == q0[i];
                    const bool m1 = ((v1[i] + sv[j]) > 0.f) == q1[i];
                    const unsigned gm0 = __ballot_sync(0xffffffffu, m0);
                    const unsigned gm1 = __ballot_sync(0xffffffffu, m1);
                    acc[j * 5 + i] += __popc(gm0) + (__popc(gm1) << 16);
                }
            }
        }
        if (lane == 0) {
            #pragma unroll
            for (int q = 0; q < 25; q++) s_ired[wid][q] = acc[q];
        }
    }
    __syncthreads();
    if (tid < 50) {
        const int bb = tid / 25, q = tid % 25;
        int t = 0;
        for (int w = 0; w < 8; w++) t += s_ired[w][q];
        const int m = bb ? (t >> 16) : (t & 0xffff);
        s_sc[bb][q] = (float)(2 * m - 1024) * (1.f / 1024.f);
    }
    __syncthreads();

    // ---- Phase 4: softmax over i (5-wide), per (batch, j) -----------------
    if (tid < 10) {
        const int bb = tid / 5, j = tid % 5;
        float mx = -1e30f;
        #pragma unroll
        for (int i = 0; i < 5; i++) mx = fmaxf(mx, s_sc[bb][j * 5 + i]);
        float e[5], sum = 0.f;
        #pragma unroll
        for (int i = 0; i < 5; i++) { e[i] = __expf(s_sc[bb][j * 5 + i] - mx); sum += e[i]; }
        const float inv = __frcp_rn(sum);
        #pragma unroll
        for (int i = 0; i < 5; i++) s_w[bb][j * 5 + i] = e[i] * inv;
    }
    __syncthreads();

    // ---- Phase 5: att = scores @ vp ; out = silu(att * sp) ----------------
    #pragma unroll
    for (int c = 0; c < S_N; c++) {
        const int idx = c * VSA_N + 4 * tid;
        const float4 sp4 = __ldg((const float4*)(g_sp + idx));
        #pragma unroll
        for (int bb = 0; bb < 2; bb++) {
            float4 att = make_float4(0.f, 0.f, 0.f, 0.f);
            #pragma unroll
            for (int i = 0; i < 5; i++) {
                const float w = s_w[bb][c * 5 + i];
                const float4 v = *(const float4*)(s_vp[bb] + i * VSA_N + 4 * tid);
                att.x = fmaf(w, v.x, att.x);
                att.y = fmaf(w, v.y, att.y);
                att.z = fmaf(w, v.z, att.z);
                att.w = fmaf(w, v.w, att.w);
            }
            float4 o4;
            o4.x = siluf(att.x * sp4.x);
            o4.y = siluf(att.y * sp4.y);
            o4.z = siluf(att.z * sp4.z);
            o4.w = siluf(att.w * sp4.w);
            *(float4*)(out + (b0 + bb) * (S_N * VSA_N) + idx) = o4;
        }
    }
}

extern "C" void kernel_launch(void* const* d_in, const int* in_sizes, int n_in,
                              void* d_out, int out_size) {
    const float* values = (const float*)d_in[0];
    const float* h      = (const float*)d_in[1];
    const float* sym    = (const float*)d_in[2];
    const float* gamma  = (const float*)d_in[3];
    const float* beta   = (const float*)d_in[4];
    float* out = (float*)d_out;

    prep_kernel<<<S_N, 256>>>(h, sym, gamma, beta);
    main_kernel<<<B_N / 2, 256>>>(values, gamma, beta, out);
}